// round 1
// baseline (speedup 1.0000x reference)
// SCNNModel — fused spherical-CNN UNet, fp32 baseline.
// Structure: 9x expand_we (weight expansion) + 8x fused (sconv+concat+nonlin)
// layers + 1 final sconv. All intermediates in __device__ scratch.
#include <cuda_runtime.h>
#include <math.h>

#define BATCH   16384
#define NCOEF   45
#define NDIR    100
#define CPAD    48      // padded coeff stride (float4-friendly)
#define TPAD    104     // padded dir stride (float4-friendly)
#define NTHR    256
#define TBATCH  4
#define OCHUNK  16

// ---------------- device scratch (allocation-free) ----------------
__device__ float g_we[1109520];                 // expanded sconv weights, all layers
__device__ float g_e1[BATCH * 16  * NCOEF];
__device__ float g_e2[BATCH * 32  * NCOEF];
__device__ float g_e3[BATCH * 64  * NCOEF];
__device__ float g_e4[BATCH * 128 * NCOEF];
__device__ float g_d1[BATCH * 128 * NCOEF];
__device__ float g_d2[BATCH * 64  * NCOEF];
__device__ float g_d3[BATCH * 32  * NCOEF];
__device__ float g_d4[BATCH * 16  * NCOEF];

// we[o][i][c] = w[o][i][ls[c]/2] * sqrt(pi / (2*ls[c]+1))
__global__ void expand_we_kernel(const float* __restrict__ w,
                                 const int* __restrict__ ls,
                                 float* __restrict__ we, int total)
{
    int idx = blockIdx.x * blockDim.x + threadIdx.x;
    if (idx >= total) return;
    int c  = idx % NCOEF;
    int oi = idx / NCOEF;
    int l  = ls[c];
    float lfac = sqrtf(3.14159265358979323846f / (2.0f * (float)l + 1.0f));
    we[idx] = w[oi * 5 + (l >> 1)] * lfac;
}

// Fused layer: out[b][oo][c] for oo in [0, O+OS):
//   oo <  O : y = sconv(in, we) row
//   oo >= O : y = skip row (channel concat)
// then nonlin: out = sft @ relu(isft @ y) along the coeff axis.
template<int I, int O, int OS>
__global__ void __launch_bounds__(NTHR)
layer_fused(const float* __restrict__ in, const float* __restrict__ skip,
            const float* __restrict__ we, const float* __restrict__ sft,
            const float* __restrict__ isft, float* __restrict__ out)
{
    constexpr int OO = O + OS;
    extern __shared__ float sm[];
    float* xs   = sm;                               // [TBATCH][I][CPAD]
    float* sis  = xs  + TBATCH * I * CPAD;          // [NCOEF][TPAD]  isft^T: [c][d]
    float* sst  = sis + NCOEF * TPAD;               // [NDIR][CPAD]   sft^T:  [d][c]
    float* ybuf = sst + NDIR * CPAD;                // [TBATCH][OCHUNK][CPAD]
    float* tbuf = ybuf + TBATCH * OCHUNK * CPAD;    // [TBATCH][OCHUNK][TPAD]

    const int tid = threadIdx.x;
    const int b0  = blockIdx.x * TBATCH;

    // stage transforms into smem (transposed for float4 inner-dim access)
    for (int idx = tid; idx < NDIR * NCOEF; idx += NTHR) {
        int d = idx / NCOEF, c = idx % NCOEF;
        sis[c * TPAD + d] = isft[idx];              // isft is [100][45]
    }
    for (int idx = tid; idx < NCOEF * NDIR; idx += NTHR) {
        int c = idx / NDIR, d = idx % NDIR;
        sst[d * CPAD + c] = sft[idx];               // sft is [45][100]
    }
    // stage input tile
    for (int idx = tid; idx < TBATCH * I * NCOEF; idx += NTHR) {
        int c = idx % NCOEF;
        int t = idx / NCOEF;
        int i = t % I, b = t / I;
        xs[(b * I + i) * CPAD + c] = in[(size_t)b0 * I * NCOEF + idx];
    }
    __syncthreads();

    for (int ob = 0; ob < OO; ob += OCHUNK) {
        // ---- stage B: produce ybuf[b][oc][c] for 16 output channels ----
        if (ob < O) {
            // register tile: 4 batch rows x 4 output channels per thread
            if (tid < 4 * NCOEF) {
                int og = tid / NCOEF;
                int c  = tid % NCOEF;
                int o0 = ob + og * 4;
                float acc[4][4];
                #pragma unroll
                for (int b = 0; b < 4; b++)
                    #pragma unroll
                    for (int j = 0; j < 4; j++) acc[b][j] = 0.f;
                const float* wp = we + (size_t)o0 * I * NCOEF + c;
                const float* xp = xs + c;
                #pragma unroll 4
                for (int i = 0; i < I; i++) {
                    float w0 = wp[(0 * I + i) * NCOEF];
                    float w1 = wp[(1 * I + i) * NCOEF];
                    float w2 = wp[(2 * I + i) * NCOEF];
                    float w3 = wp[(3 * I + i) * NCOEF];
                    #pragma unroll
                    for (int b = 0; b < 4; b++) {
                        float xv = xp[(b * I + i) * CPAD];
                        acc[b][0] += xv * w0;
                        acc[b][1] += xv * w1;
                        acc[b][2] += xv * w2;
                        acc[b][3] += xv * w3;
                    }
                }
                #pragma unroll
                for (int b = 0; b < 4; b++)
                    #pragma unroll
                    for (int j = 0; j < 4; j++)
                        ybuf[(b * OCHUNK + og * 4 + j) * CPAD + c] = acc[b][j];
            }
        } else {
            if constexpr (OS > 0) {
                // channel-concat: copy skip rows straight into the nonlin input
                for (int idx = tid; idx < TBATCH * OCHUNK * NCOEF; idx += NTHR) {
                    int c  = idx % NCOEF;
                    int t  = idx / NCOEF;
                    int oc = t % OCHUNK, b = t / OCHUNK;
                    int os = ob - O + oc;
                    ybuf[(b * OCHUNK + oc) * CPAD + c] =
                        skip[((size_t)(b0 + b) * OS + os) * NCOEF + c];
                }
            }
        }
        __syncthreads();

        // ---- stage C: tbuf[b][oc][d] = relu( sum_c isft[d][c] * y[b][oc][c] ) ----
        for (int idx = tid; idx < TBATCH * 4 * 25; idx += NTHR) {
            int dg = idx % 25;
            int t  = idx / 25;
            int og = t % 4, b = t / 4;
            int d0 = dg * 4;
            float a[4][4];
            #pragma unroll
            for (int j = 0; j < 4; j++)
                #pragma unroll
                for (int k = 0; k < 4; k++) a[j][k] = 0.f;
            const float* yb = ybuf + (b * OCHUNK + og * 4) * CPAD;
            #pragma unroll 3
            for (int c = 0; c < NCOEF; c++) {
                float4 iv = *(const float4*)(sis + c * TPAD + d0);
                #pragma unroll
                for (int j = 0; j < 4; j++) {
                    float yv = yb[j * CPAD + c];
                    a[j][0] += yv * iv.x;
                    a[j][1] += yv * iv.y;
                    a[j][2] += yv * iv.z;
                    a[j][3] += yv * iv.w;
                }
            }
            #pragma unroll
            for (int j = 0; j < 4; j++) {
                float4 r;
                r.x = fmaxf(a[j][0], 0.f);
                r.y = fmaxf(a[j][1], 0.f);
                r.z = fmaxf(a[j][2], 0.f);
                r.w = fmaxf(a[j][3], 0.f);
                *(float4*)(tbuf + (b * OCHUNK + og * 4 + j) * TPAD + d0) = r;
            }
        }
        __syncthreads();

        // ---- stage D: out[b][oo][c] = sum_d sft[c][d] * tbuf[b][oc][d] ----
        for (int idx = tid; idx < TBATCH * 4 * 12; idx += NTHR) {
            int cg = idx % 12;
            int t  = idx / 12;
            int og = t % 4, b = t / 4;
            int c0 = cg * 4;
            float a[4][4];
            #pragma unroll
            for (int j = 0; j < 4; j++)
                #pragma unroll
                for (int k = 0; k < 4; k++) a[j][k] = 0.f;
            const float* tb = tbuf + (b * OCHUNK + og * 4) * TPAD;
            #pragma unroll 4
            for (int d = 0; d < NDIR; d++) {
                float4 sv = *(const float4*)(sst + d * CPAD + c0);
                #pragma unroll
                for (int j = 0; j < 4; j++) {
                    float tv = tb[j * TPAD + d];
                    a[j][0] += tv * sv.x;
                    a[j][1] += tv * sv.y;
                    a[j][2] += tv * sv.z;
                    a[j][3] += tv * sv.w;
                }
            }
            size_t base = ((size_t)(b0 + b) * OO + (ob + og * 4)) * NCOEF + c0;
            #pragma unroll
            for (int j = 0; j < 4; j++)
                #pragma unroll
                for (int k = 0; k < 4; k++)
                    if (c0 + k < NCOEF)
                        out[base + (size_t)j * NCOEF + k] = a[j][k];
        }
        __syncthreads();
    }
}

// final layer: out[b][c] = sum_i d4[b][i][c] * we9[0][i][c]
__global__ void final_sconv(const float* __restrict__ d4,
                            const float* __restrict__ we,
                            float* __restrict__ out)
{
    int idx = blockIdx.x * blockDim.x + threadIdx.x;
    if (idx >= BATCH * NCOEF) return;
    int c = idx % NCOEF;
    int b = idx / NCOEF;
    float acc = 0.f;
    #pragma unroll
    for (int i = 0; i < 16; i++)
        acc += d4[((size_t)b * 16 + i) * NCOEF + c] * we[i * NCOEF + c];
    out[idx] = acc;
}

static constexpr size_t smem_bytes(int I)
{
    return (size_t)4 * ((size_t)TBATCH * I * CPAD + NCOEF * TPAD + NDIR * CPAD +
                        TBATCH * OCHUNK * CPAD + TBATCH * OCHUNK * TPAD);
}

extern "C" void kernel_launch(void* const* d_in, const int* in_sizes, int n_in,
                              void* d_out, int out_size)
{
    const float* x    = (const float*)d_in[0];
    const float* sft  = (const float*)d_in[1];
    const float* isft = (const float*)d_in[2];
    const float* w[9];
    for (int k = 0; k < 9; k++) w[k] = (const float*)d_in[3 + k];
    const int* ls = (const int*)d_in[12];
    float* out = (float*)d_out;

    float *we, *e1, *e2, *e3, *e4, *d1, *d2, *d3, *d4;
    cudaGetSymbolAddress((void**)&we, g_we);
    cudaGetSymbolAddress((void**)&e1, g_e1);
    cudaGetSymbolAddress((void**)&e2, g_e2);
    cudaGetSymbolAddress((void**)&e3, g_e3);
    cudaGetSymbolAddress((void**)&e4, g_e4);
    cudaGetSymbolAddress((void**)&d1, g_d1);
    cudaGetSymbolAddress((void**)&d2, g_d2);
    cudaGetSymbolAddress((void**)&d3, g_d3);
    cudaGetSymbolAddress((void**)&d4, g_d4);

    // weight expansion (offsets in floats, layout [O][I][45] per layer)
    static const int w_oi[9]  = {64, 512, 2048, 8192, 8192, 4096, 1024, 512, 16};
    static const int w_off[9] = {0, 2880, 25920, 118080, 486720,
                                 855360, 1039680, 1085760, 1108800};
    for (int k = 0; k < 9; k++) {
        int tot = w_oi[k] * NCOEF;
        expand_we_kernel<<<(tot + 255) / 256, 256>>>(w[k], ls, we + w_off[k], tot);
    }

    const int grid = BATCH / TBATCH;

    {   auto kf = layer_fused<4, 16, 0>;
        cudaFuncSetAttribute(kf, cudaFuncAttributeMaxDynamicSharedMemorySize, (int)smem_bytes(4));
        kf<<<grid, NTHR, smem_bytes(4)>>>(x, x, we + w_off[0], sft, isft, e1); }
    {   auto kf = layer_fused<16, 32, 0>;
        cudaFuncSetAttribute(kf, cudaFuncAttributeMaxDynamicSharedMemorySize, (int)smem_bytes(16));
        kf<<<grid, NTHR, smem_bytes(16)>>>(e1, e1, we + w_off[1], sft, isft, e2); }
    {   auto kf = layer_fused<32, 64, 0>;
        cudaFuncSetAttribute(kf, cudaFuncAttributeMaxDynamicSharedMemorySize, (int)smem_bytes(32));
        kf<<<grid, NTHR, smem_bytes(32)>>>(e2, e2, we + w_off[2], sft, isft, e3); }
    {   auto kf = layer_fused<64, 128, 0>;
        cudaFuncSetAttribute(kf, cudaFuncAttributeMaxDynamicSharedMemorySize, (int)smem_bytes(64));
        kf<<<grid, NTHR, smem_bytes(64)>>>(e3, e3, we + w_off[3], sft, isft, e4); }
    {   auto kf = layer_fused<128, 64, 64>;
        cudaFuncSetAttribute(kf, cudaFuncAttributeMaxDynamicSharedMemorySize, (int)smem_bytes(128));
        kf<<<grid, NTHR, smem_bytes(128)>>>(e4, e3, we + w_off[4], sft, isft, d1); }
    {   auto kf = layer_fused<128, 32, 32>;
        cudaFuncSetAttribute(kf, cudaFuncAttributeMaxDynamicSharedMemorySize, (int)smem_bytes(128));
        kf<<<grid, NTHR, smem_bytes(128)>>>(d1, e2, we + w_off[5], sft, isft, d2); }
    {   auto kf = layer_fused<64, 16, 16>;
        cudaFuncSetAttribute(kf, cudaFuncAttributeMaxDynamicSharedMemorySize, (int)smem_bytes(64));
        kf<<<grid, NTHR, smem_bytes(64)>>>(d2, e1, we + w_off[6], sft, isft, d3); }
    {   auto kf = layer_fused<32, 16, 0>;
        cudaFuncSetAttribute(kf, cudaFuncAttributeMaxDynamicSharedMemorySize, (int)smem_bytes(32));
        kf<<<grid, NTHR, smem_bytes(32)>>>(d3, d3, we + w_off[7], sft, isft, d4); }

    final_sconv<<<(BATCH * NCOEF + 255) / 256, 256>>>(d4, we + w_off[8], out);
}

// round 2
// speedup vs baseline: 1.0367x; 1.0367x over previous
// SCNNModel — per-layer sconv (fp32) + nonlin (tf32 mma.sync, 3xTF32 split).
#include <cuda_runtime.h>
#include <math.h>

#define BATCH   16384
#define NCOEF   45

// ---------------- device scratch (allocation-free) ----------------
__device__ float g_we[1109520];
__device__ float g_yb[BATCH * 128 * NCOEF];   // sconv output staging
__device__ float g_e1[BATCH * 16  * NCOEF];
__device__ float g_e2[BATCH * 32  * NCOEF];
__device__ float g_e3[BATCH * 64  * NCOEF];
__device__ float g_e4[BATCH * 128 * NCOEF];
__device__ float g_d1[BATCH * 128 * NCOEF];
__device__ float g_d2[BATCH * 64  * NCOEF];
__device__ float g_d3[BATCH * 32  * NCOEF];
__device__ float g_d4[BATCH * 16  * NCOEF];

// we[o][i][c] = w[o][i][ls[c]/2] * sqrt(pi/(2*ls[c]+1))
__global__ void expand_we_kernel(const float* __restrict__ w,
                                 const int* __restrict__ ls,
                                 float* __restrict__ we, int total)
{
    int idx = blockIdx.x * blockDim.x + threadIdx.x;
    if (idx >= total) return;
    int c  = idx % NCOEF;
    int oi = idx / NCOEF;
    int l  = ls[c];
    float lfac = sqrtf(3.14159265358979323846f / (2.0f * (float)l + 1.0f));
    we[idx] = w[oi * 5 + (l >> 1)] * lfac;
}

// ---------------- sconv: y[b][o][c] = sum_i we[o][i][c] * x[b][i][c] ----------------
// grid (B/16, O/16), block 192 = 48 c-lanes x 4 o-groups, per-thread acc[16b][4o]
template<int I, int O>
__global__ void __launch_bounds__(192, 2)
sconv_kernel(const float* __restrict__ x, const float* __restrict__ we,
             float* __restrict__ y)
{
    constexpr int TB  = 16;
    constexpr int ICH = (I < 32) ? I : 32;
    extern __shared__ float xs[];               // [TB][ICH][48]

    const int tid = threadIdx.x;
    const int c   = tid % 48;
    const int og  = tid / 48;
    const int b0  = blockIdx.x * TB;
    const int o0  = blockIdx.y * 16 + og * 4;

    float acc[TB][4];
    #pragma unroll
    for (int b = 0; b < TB; b++)
        #pragma unroll
        for (int j = 0; j < 4; j++) acc[b][j] = 0.f;

    for (int i0 = 0; i0 < I; i0 += ICH) {
        __syncthreads();
        for (int idx = tid; idx < TB * ICH * NCOEF; idx += 192) {
            int cc = idx % NCOEF;
            int t  = idx / NCOEF;
            int ii = t % ICH;
            int b  = t / ICH;
            xs[(b * ICH + ii) * 48 + cc] =
                x[((size_t)(b0 + b) * I + (i0 + ii)) * NCOEF + cc];
        }
        __syncthreads();
        if (c < NCOEF) {
            #pragma unroll 2
            for (int ii = 0; ii < ICH; ii++) {
                const float* wp = we + ((size_t)o0 * I + (i0 + ii)) * NCOEF + c;
                float w0 = wp[0];
                float w1 = wp[(size_t)I * NCOEF];
                float w2 = wp[(size_t)2 * I * NCOEF];
                float w3 = wp[(size_t)3 * I * NCOEF];
                #pragma unroll
                for (int b = 0; b < TB; b++) {
                    float xv = xs[(b * ICH + ii) * 48 + c];
                    acc[b][0] += xv * w0;
                    acc[b][1] += xv * w1;
                    acc[b][2] += xv * w2;
                    acc[b][3] += xv * w3;
                }
            }
        }
    }
    if (c < NCOEF) {
        #pragma unroll
        for (int b = 0; b < TB; b++)
            #pragma unroll
            for (int j = 0; j < 4; j++)
                y[((size_t)(b0 + b) * O + (o0 + j)) * NCOEF + c] = acc[b][j];
    }
}

// ---------------- nonlin: out = sft @ relu(isft @ y), tf32 mma + 3xTF32 ----------------
__device__ __forceinline__ unsigned f2tf32(float v)
{
    unsigned r;
    asm("cvt.rna.tf32.f32 %0, %1;" : "=r"(r) : "f"(v));
    return r;
}
__device__ __forceinline__ void split2(float v, float& hi, float& lo)
{
    unsigned h = f2tf32(v);
    hi = __uint_as_float(h);
    lo = __uint_as_float(f2tf32(v - hi));
}
__device__ __forceinline__ void mma_tf32(float* d,
    unsigned a0, unsigned a1, unsigned a2, unsigned a3,
    unsigned b0, unsigned b1)
{
    asm volatile(
        "mma.sync.aligned.m16n8k8.row.col.f32.tf32.tf32.f32 "
        "{%0,%1,%2,%3}, {%4,%5,%6,%7}, {%8,%9}, {%0,%1,%2,%3};\n"
        : "+f"(d[0]), "+f"(d[1]), "+f"(d[2]), "+f"(d[3])
        : "r"(a0), "r"(a1), "r"(a2), "r"(a3), "r"(b0), "r"(b1));
}

// smem float offsets
#define BI_ELEMS (48 * 104)
#define BS_ELEMS (104 * 56)
#define YS_ELEMS (128 * 52)
#define TS_ELEMS (128 * 108)
#define NL_SMEM  ((2 * BI_ELEMS + 2 * BS_ELEMS + YS_ELEMS + TS_ELEMS) * 4)

template<int OO, int O, int OS>
__global__ void __launch_bounds__(256, 1)
nonlin_kernel(const float* __restrict__ y, const float* __restrict__ skip,
              const float* __restrict__ isft, const float* __restrict__ sft,
              float* __restrict__ out)
{
    extern __shared__ float sm[];
    float* bi_h = sm;                       // [48][104]  isft^T hi
    float* bi_l = bi_h + BI_ELEMS;
    float* bs_h = bi_l + BI_ELEMS;          // [104][56]  sft^T hi
    float* bs_l = bs_h + BS_ELEMS;
    float* ys   = bs_l + BS_ELEMS;          // [128][52]
    float* ts   = ys + YS_ELEMS;            // [128][108]

    const int tid  = threadIdx.x;
    const int wid  = tid >> 5;
    const int lane = tid & 31;
    const int gid  = lane >> 2;
    const int tig  = lane & 3;
    const int mb   = wid * 16;

    for (int idx = tid; idx < BI_ELEMS; idx += 256) {
        int cc = idx / 104, d = idx % 104;
        float v = (cc < 45 && d < 100) ? isft[d * 45 + cc] : 0.f;
        float h, l; split2(v, h, l);
        bi_h[idx] = h; bi_l[idx] = l;
    }
    for (int idx = tid; idx < BS_ELEMS; idx += 256) {
        int d = idx / 56, cc = idx % 56;
        float v = (d < 100 && cc < 45) ? sft[cc * 100 + d] : 0.f;
        float h, l; split2(v, h, l);
        bs_h[idx] = h; bs_l[idx] = l;
    }

    const int NT = (BATCH * OO) / 128;
    for (int tile = blockIdx.x; tile < NT; tile += gridDim.x) {
        __syncthreads();
        // stage y tile [128][52] (zero-padded cols)
        for (int idx = tid; idx < YS_ELEMS; idx += 256) {
            int r = idx / 52, cc = idx % 52;
            float v = 0.f;
            if (cc < 45) {
                int gr = tile * 128 + r;
                int b = gr / OO, oo = gr % OO;
                if (OS == 0 || oo < O)
                    v = y[((size_t)b * O + oo) * 45 + cc];
                else
                    v = skip[((size_t)b * OS + (oo - O)) * 45 + cc];
            }
            ys[idx] = v;
        }
        __syncthreads();

        // GEMM1: t[128,104] = ys[128,48] * bi[48,104]
        float acc[13][4];
        #pragma unroll
        for (int nt = 0; nt < 13; nt++)
            #pragma unroll
            for (int j = 0; j < 4; j++) acc[nt][j] = 0.f;

        #pragma unroll
        for (int k0 = 0; k0 < 48; k0 += 8) {
            const float* yr = ys + (mb + gid) * 52 + k0 + tig;
            float a0 = yr[0],      a2 = yr[4];
            float a1 = yr[8 * 52], a3 = yr[8 * 52 + 4];
            float h0, l0, h1, l1, h2, l2, h3, l3;
            split2(a0, h0, l0); split2(a1, h1, l1);
            split2(a2, h2, l2); split2(a3, h3, l3);
            unsigned Ah0 = __float_as_uint(h0), Ah1 = __float_as_uint(h1);
            unsigned Ah2 = __float_as_uint(h2), Ah3 = __float_as_uint(h3);
            unsigned Al0 = __float_as_uint(l0), Al1 = __float_as_uint(l1);
            unsigned Al2 = __float_as_uint(l2), Al3 = __float_as_uint(l3);
            const int kk = k0 + tig;
            #pragma unroll
            for (int nt = 0; nt < 13; nt++) {
                unsigned bh0 = __float_as_uint(bi_h[kk * 104 + nt * 8 + gid]);
                unsigned bh1 = __float_as_uint(bi_h[(kk + 4) * 104 + nt * 8 + gid]);
                unsigned bl0 = __float_as_uint(bi_l[kk * 104 + nt * 8 + gid]);
                unsigned bl1 = __float_as_uint(bi_l[(kk + 4) * 104 + nt * 8 + gid]);
                mma_tf32(acc[nt], Ah0, Ah1, Ah2, Ah3, bh0, bh1);
                mma_tf32(acc[nt], Ah0, Ah1, Ah2, Ah3, bl0, bl1);
                mma_tf32(acc[nt], Al0, Al1, Al2, Al3, bh0, bh1);
            }
        }
        // relu -> ts
        #pragma unroll
        for (int nt = 0; nt < 13; nt++) {
            int cb = nt * 8 + 2 * tig;
            int r0 = mb + gid;
            ts[r0 * 108 + cb]           = fmaxf(acc[nt][0], 0.f);
            ts[r0 * 108 + cb + 1]       = fmaxf(acc[nt][1], 0.f);
            ts[(r0 + 8) * 108 + cb]     = fmaxf(acc[nt][2], 0.f);
            ts[(r0 + 8) * 108 + cb + 1] = fmaxf(acc[nt][3], 0.f);
        }
        __syncthreads();

        // GEMM2: out[128,48] = ts[128,104] * bs[104,48]
        float acc2[6][4];
        #pragma unroll
        for (int nt = 0; nt < 6; nt++)
            #pragma unroll
            for (int j = 0; j < 4; j++) acc2[nt][j] = 0.f;

        #pragma unroll
        for (int k0 = 0; k0 < 104; k0 += 8) {
            const float* tr = ts + (mb + gid) * 108 + k0 + tig;
            float a0 = tr[0],       a2 = tr[4];
            float a1 = tr[8 * 108], a3 = tr[8 * 108 + 4];
            float h0, l0, h1, l1, h2, l2, h3, l3;
            split2(a0, h0, l0); split2(a1, h1, l1);
            split2(a2, h2, l2); split2(a3, h3, l3);
            unsigned Ah0 = __float_as_uint(h0), Ah1 = __float_as_uint(h1);
            unsigned Ah2 = __float_as_uint(h2), Ah3 = __float_as_uint(h3);
            unsigned Al0 = __float_as_uint(l0), Al1 = __float_as_uint(l1);
            unsigned Al2 = __float_as_uint(l2), Al3 = __float_as_uint(l3);
            const int kk = k0 + tig;
            #pragma unroll
            for (int nt = 0; nt < 6; nt++) {
                unsigned bh0 = __float_as_uint(bs_h[kk * 56 + nt * 8 + gid]);
                unsigned bh1 = __float_as_uint(bs_h[(kk + 4) * 56 + nt * 8 + gid]);
                unsigned bl0 = __float_as_uint(bs_l[kk * 56 + nt * 8 + gid]);
                unsigned bl1 = __float_as_uint(bs_l[(kk + 4) * 56 + nt * 8 + gid]);
                mma_tf32(acc2[nt], Ah0, Ah1, Ah2, Ah3, bh0, bh1);
                mma_tf32(acc2[nt], Ah0, Ah1, Ah2, Ah3, bl0, bl1);
                mma_tf32(acc2[nt], Al0, Al1, Al2, Al3, bh0, bh1);
            }
        }
        // write out [128 rows][45 cols]
        {
            size_t gr0 = (size_t)tile * 128 + mb + gid;
            #pragma unroll
            for (int nt = 0; nt < 6; nt++) {
                int cb = nt * 8 + 2 * tig;
                if (cb < 45) {
                    out[gr0 * 45 + cb]       = acc2[nt][0];
                    out[(gr0 + 8) * 45 + cb] = acc2[nt][2];
                    if (cb + 1 < 45) {
                        out[gr0 * 45 + cb + 1]       = acc2[nt][1];
                        out[(gr0 + 8) * 45 + cb + 1] = acc2[nt][3];
                    }
                }
            }
        }
    }
}

// final layer: out[b][c] = sum_i d4[b][i][c] * we9[0][i][c]
__global__ void final_sconv(const float* __restrict__ d4,
                            const float* __restrict__ we,
                            float* __restrict__ out)
{
    int idx = blockIdx.x * blockDim.x + threadIdx.x;
    if (idx >= BATCH * NCOEF) return;
    int c = idx % NCOEF;
    int b = idx / NCOEF;
    float acc = 0.f;
    #pragma unroll
    for (int i = 0; i < 16; i++)
        acc += d4[((size_t)b * 16 + i) * NCOEF + c] * we[i * NCOEF + c];
    out[idx] = acc;
}

// ---------------- launch ----------------
template<int I, int O>
static void run_sconv(const float* in, const float* we, float* y)
{
    constexpr int ICH = (I < 32) ? I : 32;
    size_t smem = (size_t)16 * ICH * 48 * 4;
    auto kf = sconv_kernel<I, O>;
    cudaFuncSetAttribute(kf, cudaFuncAttributeMaxDynamicSharedMemorySize, (int)smem);
    dim3 grid(BATCH / 16, O / 16);
    kf<<<grid, 192, smem>>>(in, we, y);
}

template<int OO, int O, int OS>
static void run_nonlin(const float* y, const float* skip,
                       const float* isft, const float* sft, float* out)
{
    auto kf = nonlin_kernel<OO, O, OS>;
    cudaFuncSetAttribute(kf, cudaFuncAttributeMaxDynamicSharedMemorySize, NL_SMEM);
    kf<<<148, 256, NL_SMEM>>>(y, skip, isft, sft, out);
}

extern "C" void kernel_launch(void* const* d_in, const int* in_sizes, int n_in,
                              void* d_out, int out_size)
{
    const float* x    = (const float*)d_in[0];
    const float* sft  = (const float*)d_in[1];
    const float* isft = (const float*)d_in[2];
    const float* w[9];
    for (int k = 0; k < 9; k++) w[k] = (const float*)d_in[3 + k];
    const int* ls = (const int*)d_in[12];
    float* out = (float*)d_out;

    float *we, *yb, *e1, *e2, *e3, *e4, *d1, *d2, *d3, *d4;
    cudaGetSymbolAddress((void**)&we, g_we);
    cudaGetSymbolAddress((void**)&yb, g_yb);
    cudaGetSymbolAddress((void**)&e1, g_e1);
    cudaGetSymbolAddress((void**)&e2, g_e2);
    cudaGetSymbolAddress((void**)&e3, g_e3);
    cudaGetSymbolAddress((void**)&e4, g_e4);
    cudaGetSymbolAddress((void**)&d1, g_d1);
    cudaGetSymbolAddress((void**)&d2, g_d2);
    cudaGetSymbolAddress((void**)&d3, g_d3);
    cudaGetSymbolAddress((void**)&d4, g_d4);

    static const int w_oi[9]  = {64, 512, 2048, 8192, 8192, 4096, 1024, 512, 16};
    static const int w_off[9] = {0, 2880, 25920, 118080, 486720,
                                 855360, 1039680, 1085760, 1108800};
    for (int k = 0; k < 9; k++) {
        int tot = w_oi[k] * NCOEF;
        expand_we_kernel<<<(tot + 255) / 256, 256>>>(w[k], ls, we + w_off[k], tot);
    }

    run_sconv<4, 16>(x, we + w_off[0], yb);
    run_nonlin<16, 16, 0>(yb, yb, isft, sft, e1);

    run_sconv<16, 32>(e1, we + w_off[1], yb);
    run_nonlin<32, 32, 0>(yb, yb, isft, sft, e2);

    run_sconv<32, 64>(e2, we + w_off[2], yb);
    run_nonlin<64, 64, 0>(yb, yb, isft, sft, e3);

    run_sconv<64, 128>(e3, we + w_off[3], yb);
    run_nonlin<128, 128, 0>(yb, yb, isft, sft, e4);

    run_sconv<128, 64>(e4, we + w_off[4], yb);
    run_nonlin<128, 64, 64>(yb, e3, isft, sft, d1);

    run_sconv<128, 32>(d1, we + w_off[5], yb);
    run_nonlin<64, 32, 32>(yb, e2, isft, sft, d2);

    run_sconv<64, 16>(d2, we + w_off[6], yb);
    run_nonlin<32, 16, 16>(yb, e1, isft, sft, d3);

    run_sconv<32, 16>(d3, we + w_off[7], yb);
    run_nonlin<16, 16, 0>(yb, yb, isft, sft, d4);

    final_sconv<<<(BATCH * NCOEF + 255) / 256, 256>>>(d4, we + w_off[8], out);
}

// round 4
// speedup vs baseline: 1.3814x; 1.3326x over previous
// SCNNModel — fp32x2 (packed FFMA2) implementation.
// sconv: packed over coefficient pairs. nonlin: packed over output columns.
#include <cuda_runtime.h>
#include <math.h>
#include <stdint.h>

#define BATCH 16384
#define NCOEF 45
typedef unsigned long long u64;

// ---------------- device scratch ----------------
__device__ float g_we[1183488];               // pair-padded weights [o][i][48]
__device__ float g_yb[BATCH * 128 * NCOEF];
__device__ float g_e1[BATCH * 16  * NCOEF];
__device__ float g_e2[BATCH * 32  * NCOEF];
__device__ float g_e3[BATCH * 64  * NCOEF];
__device__ float g_e4[BATCH * 128 * NCOEF];
__device__ float g_d1[BATCH * 128 * NCOEF];
__device__ float g_d2[BATCH * 64  * NCOEF];
__device__ float g_d3[BATCH * 32  * NCOEF];
__device__ float g_d4[BATCH * 16  * NCOEF];

// ---------------- f32x2 helpers ----------------
__device__ __forceinline__ u64 pack2(float x, float y) {
    u64 r;
    asm("mov.b64 %0, {%1, %2};" : "=l"(r) : "f"(x), "f"(y));
    return r;
}
__device__ __forceinline__ void unpack2(u64 v, float& x, float& y) {
    asm("mov.b64 {%0, %1}, %2;" : "=f"(x), "=f"(y) : "l"(v));
}
__device__ __forceinline__ void fma2(u64& d, u64 a, u64 b) {
    asm("fma.rn.f32x2 %0, %1, %2, %0;" : "+l"(d) : "l"(a), "l"(b));
}

// ---------------- expand: w -> pair-padded we [o][i][48] ----------------
__global__ void expand_all_kernel(const float* w1, const float* w2, const float* w3,
                                  const float* w4, const float* w5, const float* w6,
                                  const float* w7, const float* w8, const float* w9,
                                  const int* __restrict__ ls, float* __restrict__ we)
{
    int idx = blockIdx.x * blockDim.x + threadIdx.x;
    if (idx >= 1183488) return;
    const int cum[10] = {0, 3072, 27648, 125952, 519168, 912384,
                         1108992, 1158144, 1182720, 1183488};
    const float* ws[9] = {w1, w2, w3, w4, w5, w6, w7, w8, w9};
    int k = 0;
    #pragma unroll
    for (int j = 1; j < 9; j++) if (idx >= cum[j]) k = j;
    int local = idx - cum[k];
    int c  = local % 48;
    int oi = local / 48;
    float v = 0.f;
    if (c < 45) {
        int l = ls[c];
        float lfac = sqrtf(3.14159265358979323846f / (2.0f * (float)l + 1.0f));
        v = ws[k][oi * 5 + (l >> 1)] * lfac;
    }
    we[idx] = v;
}

// ---------------- sconv: y[b][o][c] = sum_i we[o][i][c]*x[b][i][c] (f32x2 over c-pairs) ----
template<int I, int O>
__global__ void __launch_bounds__(192)
sconv2(const float* __restrict__ x, const float* __restrict__ we,
       float* __restrict__ y)
{
    constexpr int OCTA = (O >= 32) ? 32 : 16;
    constexpr int OGO  = OCTA / 8;            // o-channels per o-group (4 or 2)
    constexpr int ICH  = (I < 32) ? I : 32;
    extern __shared__ float xs[];             // [16][ICH][48]

    const int tid = threadIdx.x;
    const int cp  = tid % 24;                 // coefficient pair lane
    const int og  = tid / 24;                 // o-group 0..7
    const int b0  = blockIdx.x * 16;
    const int o0  = blockIdx.y * OCTA + og * OGO;

    u64 acc[16][OGO];
    #pragma unroll
    for (int b = 0; b < 16; b++)
        #pragma unroll
        for (int j = 0; j < OGO; j++) acc[b][j] = 0ull;

    for (int i0 = 0; i0 < I; i0 += ICH) {
        __syncthreads();
        for (int idx = tid; idx < 16 * ICH * 48; idx += 192) {
            int c = idx % 48;
            int t = idx / 48;
            int ii = t % ICH, b = t / ICH;
            xs[idx] = (c < 45)
                ? x[((size_t)(b0 + b) * I + (i0 + ii)) * 45 + c] : 0.f;
        }
        __syncthreads();
        #pragma unroll 2
        for (int ii = 0; ii < ICH; ii++) {
            u64 wv[OGO];
            #pragma unroll
            for (int j = 0; j < OGO; j++)
                wv[j] = *(const u64*)(we + ((size_t)(o0 + j) * I + (i0 + ii)) * 48 + 2 * cp);
            #pragma unroll
            for (int b = 0; b < 16; b++) {
                u64 xv = *(const u64*)(xs + (b * ICH + ii) * 48 + 2 * cp);
                #pragma unroll
                for (int j = 0; j < OGO; j++) fma2(acc[b][j], xv, wv[j]);
            }
        }
    }
    const int c = 2 * cp;
    #pragma unroll
    for (int b = 0; b < 16; b++)
        #pragma unroll
        for (int j = 0; j < OGO; j++) {
            float lo, hi;
            unpack2(acc[b][j], lo, hi);
            size_t base = ((size_t)(b0 + b) * O + (o0 + j)) * 45;
            if (c < 45)     y[base + c]     = lo;
            if (c + 1 < 45) y[base + c + 1] = hi;
        }
}

// ---------------- nonlin: out = sft @ relu(isft @ y)  (f32x2) ----------------
// CTA tile: 256 rows of (b,oo). GEMM1 thread tile 8 rows x 7 d-pairs,
// GEMM2 thread tile 8 rows x 3 c-pairs. 256 threads.
#define NL_SMEM ((45*56 + 100*24) * 8 + (256*49 + 256*113) * 4)

template<int OO, int O, int OS>
__global__ void __launch_bounds__(256)
nonlin2(const float* __restrict__ y, const float* __restrict__ skip,
        const float* __restrict__ isft, const float* __restrict__ sft,
        float* __restrict__ out)
{
    extern __shared__ char smraw[];
    u64*   bi2 = (u64*)smraw;                 // [45][56]  isft, d-pairs packed
    u64*   bs2 = bi2 + 45 * 56;               // [100][24] sft,  c-pairs packed
    float* ys  = (float*)(bs2 + 100 * 24);    // [256][49]  (also out staging)
    float* ts  = ys + 256 * 49;               // [256][113]

    const int tid = threadIdx.x;
    const int rg  = tid >> 3;                 // 32 row-groups of 8 rows
    const int pg  = tid & 7;                  // 8 pair-groups
    const int tile = blockIdx.x;

    // stage B matrices (packed pairs, zero-padded)
    for (int idx = tid; idx < 45 * 56; idx += 256) {
        int k = idx / 56, p = idx % 56;
        float a = 0.f, b = 0.f;
        if (2 * p < 100) {
            a = isft[(2 * p) * 45 + k];
            b = isft[(2 * p + 1) * 45 + k];
        }
        bi2[idx] = pack2(a, b);
    }
    for (int idx = tid; idx < 100 * 24; idx += 256) {
        int d = idx / 24, p = idx % 24;
        int c = 2 * p;
        float a = (c < 45)     ? sft[c * 100 + d]       : 0.f;
        float b = (c + 1 < 45) ? sft[(c + 1) * 100 + d] : 0.f;
        bs2[idx] = pack2(a, b);
    }
    // stage input rows (concat resolved here)
    for (int idx = tid; idx < 256 * 45; idx += 256) {
        int r = idx / 45, cc = idx % 45;
        int gr = tile * 256 + r;
        int b = gr / OO, oo = gr % OO;
        float v;
        if (OS == 0 || oo < O) v = y[((size_t)b * O + oo) * 45 + cc];
        else                   v = skip[((size_t)b * OS + (oo - O)) * 45 + cc];
        ys[r * 49 + cc] = v;
    }
    __syncthreads();

    // GEMM1: t[r][d] = sum_c ys[r][c] * isft[d][c], d packed in pairs
    {
        u64 acc[8][7];
        #pragma unroll
        for (int j = 0; j < 8; j++)
            #pragma unroll
            for (int q = 0; q < 7; q++) acc[j][q] = 0ull;

        const float* yrow  = ys + rg * 8 * 49;
        const u64*   bbase = bi2 + pg * 7;
        for (int k = 0; k < 45; k++) {
            u64 ya[8];
            #pragma unroll
            for (int j = 0; j < 8; j++) {
                float v = yrow[j * 49 + k];
                ya[j] = pack2(v, v);
            }
            u64 bv[7];
            #pragma unroll
            for (int q = 0; q < 7; q++) bv[q] = bbase[k * 56 + q];
            #pragma unroll
            for (int j = 0; j < 8; j++)
                #pragma unroll
                for (int q = 0; q < 7; q++) fma2(acc[j][q], ya[j], bv[q]);
        }
        // relu -> ts
        #pragma unroll
        for (int j = 0; j < 8; j++)
            #pragma unroll
            for (int q = 0; q < 7; q++) {
                float lo, hi;
                unpack2(acc[j][q], lo, hi);
                int r = rg * 8 + j;
                int col = 2 * (pg * 7 + q);
                ts[r * 113 + col]     = fmaxf(lo, 0.f);
                ts[r * 113 + col + 1] = fmaxf(hi, 0.f);
            }
    }
    __syncthreads();

    // GEMM2: o[r][c] = sum_d ts[r][d] * sft[c][d], c packed in pairs
    {
        u64 acc2[8][3];
        #pragma unroll
        for (int j = 0; j < 8; j++)
            #pragma unroll
            for (int q = 0; q < 3; q++) acc2[j][q] = 0ull;

        const float* trow   = ts + rg * 8 * 113;
        const u64*   b2base = bs2 + pg * 3;
        for (int k = 0; k < 100; k++) {
            u64 ta[8];
            #pragma unroll
            for (int j = 0; j < 8; j++) {
                float v = trow[j * 113 + k];
                ta[j] = pack2(v, v);
            }
            u64 bv[3];
            #pragma unroll
            for (int q = 0; q < 3; q++) bv[q] = b2base[k * 24 + q];
            #pragma unroll
            for (int j = 0; j < 8; j++)
                #pragma unroll
                for (int q = 0; q < 3; q++) fma2(acc2[j][q], ta[j], bv[q]);
        }
        // stage result into ys (reuse), then coalesced copy
        #pragma unroll
        for (int j = 0; j < 8; j++)
            #pragma unroll
            for (int q = 0; q < 3; q++) {
                float lo, hi;
                unpack2(acc2[j][q], lo, hi);
                int r = rg * 8 + j;
                int c = 2 * (pg * 3 + q);
                ys[r * 49 + c] = lo;
                ys[r * 49 + c + 1] = hi;   // c+1 <= 47 < 49
            }
    }
    __syncthreads();
    size_t base = (size_t)tile * 256 * 45;
    for (int idx = tid; idx < 256 * 45; idx += 256)
        out[base + idx] = ys[(idx / 45) * 49 + idx % 45];
}

// ---------------- final sconv ----------------
__global__ void final_sconv(const float* __restrict__ d4,
                            const float* __restrict__ we,
                            float* __restrict__ out)
{
    int idx = blockIdx.x * blockDim.x + threadIdx.x;
    if (idx >= BATCH * NCOEF) return;
    int c = idx % NCOEF;
    int b = idx / NCOEF;
    float acc = 0.f;
    #pragma unroll
    for (int i = 0; i < 16; i++)
        acc += d4[((size_t)b * 16 + i) * 45 + c] * we[i * 48 + c];
    out[idx] = acc;
}

// ---------------- launch helpers ----------------
template<int I, int O>
static void run_sconv(const float* in, const float* we, float* y)
{
    constexpr int ICH  = (I < 32) ? I : 32;
    constexpr int OCTA = (O >= 32) ? 32 : 16;
    size_t smem = (size_t)16 * ICH * 48 * 4;
    auto kf = sconv2<I, O>;
    cudaFuncSetAttribute(kf, cudaFuncAttributeMaxDynamicSharedMemorySize, (int)smem);
    dim3 grid(BATCH / 16, O / OCTA);
    kf<<<grid, 192, smem>>>(in, we, y);
}

template<int OO, int O, int OS>
static void run_nonlin(const float* y, const float* skip,
                       const float* isft, const float* sft, float* out)
{
    auto kf = nonlin2<OO, O, OS>;
    cudaFuncSetAttribute(kf, cudaFuncAttributeMaxDynamicSharedMemorySize, NL_SMEM);
    kf<<<(BATCH * OO) / 256, 256, NL_SMEM>>>(y, skip, isft, sft, out);
}

extern "C" void kernel_launch(void* const* d_in, const int* in_sizes, int n_in,
                              void* d_out, int out_size)
{
    const float* x    = (const float*)d_in[0];
    const float* sft  = (const float*)d_in[1];
    const float* isft = (const float*)d_in[2];
    const float* w[9];
    for (int k = 0; k < 9; k++) w[k] = (const float*)d_in[3 + k];
    const int* ls = (const int*)d_in[12];
    float* out = (float*)d_out;

    float *we, *yb, *e1, *e2, *e3, *e4, *d1, *d2, *d3, *d4;
    cudaGetSymbolAddress((void**)&we, g_we);
    cudaGetSymbolAddress((void**)&yb, g_yb);
    cudaGetSymbolAddress((void**)&e1, g_e1);
    cudaGetSymbolAddress((void**)&e2, g_e2);
    cudaGetSymbolAddress((void**)&e3, g_e3);
    cudaGetSymbolAddress((void**)&e4, g_e4);
    cudaGetSymbolAddress((void**)&d1, g_d1);
    cudaGetSymbolAddress((void**)&d2, g_d2);
    cudaGetSymbolAddress((void**)&d3, g_d3);
    cudaGetSymbolAddress((void**)&d4, g_d4);

    // pair-padded weight offsets: [o][i][48] per layer
    static const int w_off[9] = {0, 3072, 27648, 125952, 519168,
                                 912384, 1108992, 1158144, 1182720};

    expand_all_kernel<<<(1183488 + 255) / 256, 256>>>(
        w[0], w[1], w[2], w[3], w[4], w[5], w[6], w[7], w[8], ls, we);

    run_sconv<4, 16>(x, we + w_off[0], yb);
    run_nonlin<16, 16, 0>(yb, yb, isft, sft, e1);

    run_sconv<16, 32>(e1, we + w_off[1], yb);
    run_nonlin<32, 32, 0>(yb, yb, isft, sft, e2);

    run_sconv<32, 64>(e2, we + w_off[2], yb);
    run_nonlin<64, 64, 0>(yb, yb, isft, sft, e3);

    run_sconv<64, 128>(e3, we + w_off[3], yb);
    run_nonlin<128, 128, 0>(yb, yb, isft, sft, e4);

    run_sconv<128, 64>(e4, we + w_off[4], yb);
    run_nonlin<128, 64, 64>(yb, e3, isft, sft, d1);

    run_sconv<128, 32>(d1, we + w_off[5], yb);
    run_nonlin<64, 32, 32>(yb, e2, isft, sft, d2);

    run_sconv<64, 16>(d2, we + w_off[6], yb);
    run_nonlin<32, 16, 16>(yb, e1, isft, sft, d3);

    run_sconv<32, 16>(d3, we + w_off[7], yb);
    run_nonlin<16, 16, 0>(yb, yb, isft, sft, d4);

    final_sconv<<<(BATCH * NCOEF + 255) / 256, 256>>>(d4, we + w_off[8], out);
}

// round 5
// speedup vs baseline: 1.4044x; 1.0166x over previous
// SCNNModel — fp32x2 v3: smem-staged weights in sconv, persistent slim nonlin.
#include <cuda_runtime.h>
#include <math.h>
#include <stdint.h>

#define BATCH 16384
#define NCOEF 45
typedef unsigned long long u64;

// ---------------- device scratch ----------------
__device__ float g_we[1183488];               // pair-padded weights [o][i][48]
__device__ float g_yb[BATCH * 128 * NCOEF];
__device__ float g_e1[BATCH * 16  * NCOEF];
__device__ float g_e2[BATCH * 32  * NCOEF];
__device__ float g_e3[BATCH * 64  * NCOEF];
__device__ float g_e4[BATCH * 128 * NCOEF];
__device__ float g_d1[BATCH * 128 * NCOEF];
__device__ float g_d2[BATCH * 64  * NCOEF];
__device__ float g_d3[BATCH * 32  * NCOEF];
__device__ float g_d4[BATCH * 16  * NCOEF];

// ---------------- f32x2 helpers ----------------
__device__ __forceinline__ u64 pack2(float x, float y) {
    u64 r;
    asm("mov.b64 %0, {%1, %2};" : "=l"(r) : "f"(x), "f"(y));
    return r;
}
__device__ __forceinline__ void unpack2(u64 v, float& x, float& y) {
    asm("mov.b64 {%0, %1}, %2;" : "=f"(x), "=f"(y) : "l"(v));
}
__device__ __forceinline__ void fma2(u64& d, u64 a, u64 b) {
    asm("fma.rn.f32x2 %0, %1, %2, %0;" : "+l"(d) : "l"(a), "l"(b));
}

// ---------------- expand: w -> pair-padded we [o][i][48] ----------------
__global__ void expand_all_kernel(const float* w1, const float* w2, const float* w3,
                                  const float* w4, const float* w5, const float* w6,
                                  const float* w7, const float* w8, const float* w9,
                                  const int* __restrict__ ls, float* __restrict__ we)
{
    int idx = blockIdx.x * blockDim.x + threadIdx.x;
    if (idx >= 1183488) return;
    const int cum[10] = {0, 3072, 27648, 125952, 519168, 912384,
                         1108992, 1158144, 1182720, 1183488};
    const float* ws[9] = {w1, w2, w3, w4, w5, w6, w7, w8, w9};
    int k = 0;
    #pragma unroll
    for (int j = 1; j < 9; j++) if (idx >= cum[j]) k = j;
    int local = idx - cum[k];
    int c  = local % 48;
    int oi = local / 48;
    float v = 0.f;
    if (c < 45) {
        int l = ls[c];
        float lfac = sqrtf(3.14159265358979323846f / (2.0f * (float)l + 1.0f));
        v = ws[k][oi * 5 + (l >> 1)] * lfac;
    }
    we[idx] = v;
}

// ---------------- sconv v3: weights + x both staged in smem ----------------
template<int I, int O>
__global__ void __launch_bounds__(192, 2)
sconv3(const float* __restrict__ x, const float* __restrict__ we,
       float* __restrict__ y)
{
    constexpr int OCTA = (O >= 32) ? 32 : 16;
    constexpr int OGO  = OCTA / 8;            // 4 or 2 o-channels per o-group
    constexpr int ICH  = (I < 8) ? I : 8;
    extern __shared__ float sm[];
    float* xs = sm;                           // [16][ICH][48]
    float* ws = sm + 16 * ICH * 48;           // [OCTA][ICH][48]

    const int tid = threadIdx.x;
    const int cp  = tid % 24;
    const int og  = tid / 24;
    const int b0  = blockIdx.x * 16;
    const int o0g = blockIdx.y * OCTA;

    u64 acc[16][OGO];
    #pragma unroll
    for (int b = 0; b < 16; b++)
        #pragma unroll
        for (int j = 0; j < OGO; j++) acc[b][j] = 0ull;

    for (int i0 = 0; i0 < I; i0 += ICH) {
        __syncthreads();
        for (int idx = tid; idx < 16 * ICH * 48; idx += 192) {
            int c = idx % 48;
            int t = idx / 48;
            int ii = t % ICH, b = t / ICH;
            xs[idx] = (c < 45)
                ? x[((size_t)(b0 + b) * I + (i0 + ii)) * 45 + c] : 0.f;
        }
        for (int idx = tid; idx < OCTA * ICH * 48; idx += 192) {
            int c = idx % 48;
            int t = idx / 48;
            int ii = t % ICH, o = t / ICH;
            ws[idx] = we[((size_t)(o0g + o) * I + (i0 + ii)) * 48 + c];
        }
        __syncthreads();
        #pragma unroll
        for (int ii = 0; ii < ICH; ii++) {
            u64 wv[OGO];
            #pragma unroll
            for (int j = 0; j < OGO; j++)
                wv[j] = *(const u64*)(ws + ((og * OGO + j) * ICH + ii) * 48 + 2 * cp);
            #pragma unroll
            for (int b = 0; b < 16; b++) {
                u64 xv = *(const u64*)(xs + (b * ICH + ii) * 48 + 2 * cp);
                #pragma unroll
                for (int j = 0; j < OGO; j++) fma2(acc[b][j], xv, wv[j]);
            }
        }
    }
    const int c = 2 * cp;
    #pragma unroll
    for (int b = 0; b < 16; b++)
        #pragma unroll
        for (int j = 0; j < OGO; j++) {
            float lo, hi;
            unpack2(acc[b][j], lo, hi);
            size_t base = ((size_t)(b0 + b) * O + (o0g + og * OGO + j)) * 45;
            if (c < 45)     y[base + c]     = lo;
            if (c + 1 < 45) y[base + c + 1] = hi;
        }
}

// ---------------- nonlin v3: persistent, 512 thr, 4-row x 7-pair tiles ----------------
// smem: bi2 u64[45][56] | bs2 u64[100][24] | ys f[256][46] | ts f[256][101]
#define NL_SMEM (20160 + 19200 + 47104 + 103424)

template<int OO, int O, int OS>
__global__ void __launch_bounds__(512, 1)
nonlin3(const float* __restrict__ y, const float* __restrict__ skip,
        const float* __restrict__ isft, const float* __restrict__ sft,
        float* __restrict__ out)
{
    extern __shared__ char smraw[];
    u64*   bi2 = (u64*)smraw;                 // [45][56]  isft, d-pairs packed
    u64*   bs2 = bi2 + 45 * 56;               // [100][24] sft,  c-pairs packed
    float* ys  = (float*)(bs2 + 100 * 24);    // [256][46]
    float* ts  = ys + 256 * 46;               // [256][101]

    const int tid = threadIdx.x;
    const int rg  = tid >> 3;                 // 64 row-groups of 4 rows
    const int pg  = tid & 7;                  // 8 pair-groups

    // stage B matrices once per CTA
    for (int idx = tid; idx < 45 * 56; idx += 512) {
        int k = idx / 56, p = idx % 56;
        float a = 0.f, b = 0.f;
        if (2 * p < 100) {
            a = isft[(2 * p) * 45 + k];
            b = isft[(2 * p + 1) * 45 + k];
        }
        bi2[idx] = pack2(a, b);
    }
    for (int idx = tid; idx < 100 * 24; idx += 512) {
        int d = idx / 24, p = idx % 24;
        int c = 2 * p;
        float a = (c < 45)     ? sft[c * 100 + d]       : 0.f;
        float b = (c + 1 < 45) ? sft[(c + 1) * 100 + d] : 0.f;
        bs2[idx] = pack2(a, b);
    }
    __syncthreads();

    const int NT = (BATCH * OO) / 256;
    for (int tile = blockIdx.x; tile < NT; tile += gridDim.x) {
        // stage input rows (concat resolved here)
        for (int idx = tid; idx < 256 * 45; idx += 512) {
            int r = idx / 45, cc = idx % 45;
            int gr = tile * 256 + r;
            int b = gr / OO, oo = gr % OO;
            float v;
            if (OS == 0 || oo < O) v = y[((size_t)b * O + oo) * 45 + cc];
            else                   v = skip[((size_t)b * OS + (oo - O)) * 45 + cc];
            ys[r * 46 + cc] = v;
        }
        __syncthreads();

        // GEMM1: t[r][d] = sum_c ys[r][c]*isft[d][c]; 4 rows x 7 d-pairs/thread
        {
            u64 acc[4][7];
            #pragma unroll
            for (int j = 0; j < 4; j++)
                #pragma unroll
                for (int q = 0; q < 7; q++) acc[j][q] = 0ull;

            const float* yrow = ys + rg * 4 * 46;
            const u64*   bb   = bi2 + pg * 7;
            #pragma unroll 3
            for (int k = 0; k < 45; k++) {
                u64 ya[4];
                #pragma unroll
                for (int j = 0; j < 4; j++) {
                    float v = yrow[j * 46 + k];
                    ya[j] = pack2(v, v);
                }
                u64 bv[7];
                #pragma unroll
                for (int q = 0; q < 7; q++) bv[q] = bb[k * 56 + q];
                #pragma unroll
                for (int j = 0; j < 4; j++)
                    #pragma unroll
                    for (int q = 0; q < 7; q++) fma2(acc[j][q], ya[j], bv[q]);
            }
            #pragma unroll
            for (int j = 0; j < 4; j++)
                #pragma unroll
                for (int q = 0; q < 7; q++) {
                    int col = 2 * (pg * 7 + q);
                    if (col < 100) {
                        float lo, hi;
                        unpack2(acc[j][q], lo, hi);
                        int r = rg * 4 + j;
                        ts[r * 101 + col]     = fmaxf(lo, 0.f);
                        ts[r * 101 + col + 1] = fmaxf(hi, 0.f);
                    }
                }
        }
        __syncthreads();

        // GEMM2: o[r][c] = sum_d ts[r][d]*sft[c][d]; 4 rows x 3 c-pairs/thread
        {
            u64 acc2[4][3];
            #pragma unroll
            for (int j = 0; j < 4; j++)
                #pragma unroll
                for (int q = 0; q < 3; q++) acc2[j][q] = 0ull;

            const float* trow = ts + rg * 4 * 101;
            const u64*   bb2  = bs2 + pg * 3;
            #pragma unroll 2
            for (int k = 0; k < 100; k++) {
                u64 ta[4];
                #pragma unroll
                for (int j = 0; j < 4; j++) {
                    float v = trow[j * 101 + k];
                    ta[j] = pack2(v, v);
                }
                u64 bv[3];
                #pragma unroll
                for (int q = 0; q < 3; q++) bv[q] = bb2[k * 24 + q];
                #pragma unroll
                for (int j = 0; j < 4; j++)
                    #pragma unroll
                    for (int q = 0; q < 3; q++) fma2(acc2[j][q], ta[j], bv[q]);
            }
            __syncthreads();   // ts free; also ys readers of prev phase done
            #pragma unroll
            for (int j = 0; j < 4; j++)
                #pragma unroll
                for (int q = 0; q < 3; q++) {
                    int c = 2 * (pg * 3 + q);
                    if (c < 45) {
                        float lo, hi;
                        unpack2(acc2[j][q], lo, hi);
                        int r = rg * 4 + j;
                        ys[r * 46 + c]     = lo;
                        ys[r * 46 + c + 1] = hi;
                    }
                }
        }
        __syncthreads();
        size_t base = (size_t)tile * 256 * 45;
        for (int idx = tid; idx < 256 * 45; idx += 512)
            out[base + idx] = ys[(idx / 45) * 46 + idx % 45];
        __syncthreads();
    }
}

// ---------------- final sconv ----------------
__global__ void final_sconv(const float* __restrict__ d4,
                            const float* __restrict__ we,
                            float* __restrict__ out)
{
    int idx = blockIdx.x * blockDim.x + threadIdx.x;
    if (idx >= BATCH * NCOEF) return;
    int c = idx % NCOEF;
    int b = idx / NCOEF;
    float acc = 0.f;
    #pragma unroll
    for (int i = 0; i < 16; i++)
        acc += d4[((size_t)b * 16 + i) * 45 + c] * we[i * 48 + c];
    out[idx] = acc;
}

// ---------------- launch helpers ----------------
template<int I, int O>
static void run_sconv(const float* in, const float* we, float* y)
{
    constexpr int OCTA = (O >= 32) ? 32 : 16;
    constexpr int ICH  = (I < 8) ? I : 8;
    size_t smem = (size_t)(16 + OCTA) * ICH * 48 * 4;
    auto kf = sconv3<I, O>;
    cudaFuncSetAttribute(kf, cudaFuncAttributeMaxDynamicSharedMemorySize, (int)smem);
    dim3 grid(BATCH / 16, O / OCTA);
    kf<<<grid, 192, smem>>>(in, we, y);
}

template<int OO, int O, int OS>
static void run_nonlin(const float* y, const float* skip,
                       const float* isft, const float* sft, float* out)
{
    auto kf = nonlin3<OO, O, OS>;
    cudaFuncSetAttribute(kf, cudaFuncAttributeMaxDynamicSharedMemorySize, NL_SMEM);
    kf<<<148, 512, NL_SMEM>>>(y, skip, isft, sft, out);
}

extern "C" void kernel_launch(void* const* d_in, const int* in_sizes, int n_in,
                              void* d_out, int out_size)
{
    const float* x    = (const float*)d_in[0];
    const float* sft  = (const float*)d_in[1];
    const float* isft = (const float*)d_in[2];
    const float* w[9];
    for (int k = 0; k < 9; k++) w[k] = (const float*)d_in[3 + k];
    const int* ls = (const int*)d_in[12];
    float* out = (float*)d_out;

    float *we, *yb, *e1, *e2, *e3, *e4, *d1, *d2, *d3, *d4;
    cudaGetSymbolAddress((void**)&we, g_we);
    cudaGetSymbolAddress((void**)&yb, g_yb);
    cudaGetSymbolAddress((void**)&e1, g_e1);
    cudaGetSymbolAddress((void**)&e2, g_e2);
    cudaGetSymbolAddress((void**)&e3, g_e3);
    cudaGetSymbolAddress((void**)&e4, g_e4);
    cudaGetSymbolAddress((void**)&d1, g_d1);
    cudaGetSymbolAddress((void**)&d2, g_d2);
    cudaGetSymbolAddress((void**)&d3, g_d3);
    cudaGetSymbolAddress((void**)&d4, g_d4);

    static const int w_off[9] = {0, 3072, 27648, 125952, 519168,
                                 912384, 1108992, 1158144, 1182720};

    expand_all_kernel<<<(1183488 + 255) / 256, 256>>>(
        w[0], w[1], w[2], w[3], w[4], w[5], w[6], w[7], w[8], ls, we);

    run_sconv<4, 16>(x, we + w_off[0], yb);
    run_nonlin<16, 16, 0>(yb, yb, isft, sft, e1);

    run_sconv<16, 32>(e1, we + w_off[1], yb);
    run_nonlin<32, 32, 0>(yb, yb, isft, sft, e2);

    run_sconv<32, 64>(e2, we + w_off[2], yb);
    run_nonlin<64, 64, 0>(yb, yb, isft, sft, e3);

    run_sconv<64, 128>(e3, we + w_off[3], yb);
    run_nonlin<128, 128, 0>(yb, yb, isft, sft, e4);

    run_sconv<128, 64>(e4, we + w_off[4], yb);
    run_nonlin<128, 64, 64>(yb, e3, isft, sft, d1);

    run_sconv<128, 32>(d1, we + w_off[5], yb);
    run_nonlin<64, 32, 32>(yb, e2, isft, sft, d2);

    run_sconv<64, 16>(d2, we + w_off[6], yb);
    run_nonlin<32, 16, 16>(yb, e1, isft, sft, d3);

    run_sconv<32, 16>(d3, we + w_off[7], yb);
    run_nonlin<16, 16, 0>(yb, yb, isft, sft, d4);

    final_sconv<<<(BATCH * NCOEF + 255) / 256, 256>>>(d4, we + w_off[8], out);
}

// round 6
// speedup vs baseline: 1.4051x; 1.0005x over previous
// SCNNModel — fp32x2 v3: smem-staged weights in sconv, persistent slim nonlin.
#include <cuda_runtime.h>
#include <math.h>
#include <stdint.h>

#define BATCH 16384
#define NCOEF 45
typedef unsigned long long u64;

// ---------------- device scratch ----------------
__device__ float g_we[1183488];               // pair-padded weights [o][i][48]
__device__ float g_yb[BATCH * 128 * NCOEF];
__device__ float g_e1[BATCH * 16  * NCOEF];
__device__ float g_e2[BATCH * 32  * NCOEF];
__device__ float g_e3[BATCH * 64  * NCOEF];
__device__ float g_e4[BATCH * 128 * NCOEF];
__device__ float g_d1[BATCH * 128 * NCOEF];
__device__ float g_d2[BATCH * 64  * NCOEF];
__device__ float g_d3[BATCH * 32  * NCOEF];
__device__ float g_d4[BATCH * 16  * NCOEF];

// ---------------- f32x2 helpers ----------------
__device__ __forceinline__ u64 pack2(float x, float y) {
    u64 r;
    asm("mov.b64 %0, {%1, %2};" : "=l"(r) : "f"(x), "f"(y));
    return r;
}
__device__ __forceinline__ void unpack2(u64 v, float& x, float& y) {
    asm("mov.b64 {%0, %1}, %2;" : "=f"(x), "=f"(y) : "l"(v));
}
__device__ __forceinline__ void fma2(u64& d, u64 a, u64 b) {
    asm("fma.rn.f32x2 %0, %1, %2, %0;" : "+l"(d) : "l"(a), "l"(b));
}

// ---------------- expand: w -> pair-padded we [o][i][48] ----------------
__global__ void expand_all_kernel(const float* w1, const float* w2, const float* w3,
                                  const float* w4, const float* w5, const float* w6,
                                  const float* w7, const float* w8, const float* w9,
                                  const int* __restrict__ ls, float* __restrict__ we)
{
    int idx = blockIdx.x * blockDim.x + threadIdx.x;
    if (idx >= 1183488) return;
    const int cum[10] = {0, 3072, 27648, 125952, 519168, 912384,
                         1108992, 1158144, 1182720, 1183488};
    const float* ws[9] = {w1, w2, w3, w4, w5, w6, w7, w8, w9};
    int k = 0;
    #pragma unroll
    for (int j = 1; j < 9; j++) if (idx >= cum[j]) k = j;
    int local = idx - cum[k];
    int c  = local % 48;
    int oi = local / 48;
    float v = 0.f;
    if (c < 45) {
        int l = ls[c];
        float lfac = sqrtf(3.14159265358979323846f / (2.0f * (float)l + 1.0f));
        v = ws[k][oi * 5 + (l >> 1)] * lfac;
    }
    we[idx] = v;
}

// ---------------- sconv v3: weights + x both staged in smem ----------------
template<int I, int O>
__global__ void __launch_bounds__(192, 2)
sconv3(const float* __restrict__ x, const float* __restrict__ we,
       float* __restrict__ y)
{
    constexpr int OCTA = (O >= 32) ? 32 : 16;
    constexpr int OGO  = OCTA / 8;            // 4 or 2 o-channels per o-group
    constexpr int ICH  = (I < 8) ? I : 8;
    extern __shared__ float sm[];
    float* xs = sm;                           // [16][ICH][48]
    float* ws = sm + 16 * ICH * 48;           // [OCTA][ICH][48]

    const int tid = threadIdx.x;
    const int cp  = tid % 24;
    const int og  = tid / 24;
    const int b0  = blockIdx.x * 16;
    const int o0g = blockIdx.y * OCTA;

    u64 acc[16][OGO];
    #pragma unroll
    for (int b = 0; b < 16; b++)
        #pragma unroll
        for (int j = 0; j < OGO; j++) acc[b][j] = 0ull;

    for (int i0 = 0; i0 < I; i0 += ICH) {
        __syncthreads();
        for (int idx = tid; idx < 16 * ICH * 48; idx += 192) {
            int c = idx % 48;
            int t = idx / 48;
            int ii = t % ICH, b = t / ICH;
            xs[idx] = (c < 45)
                ? x[((size_t)(b0 + b) * I + (i0 + ii)) * 45 + c] : 0.f;
        }
        for (int idx = tid; idx < OCTA * ICH * 48; idx += 192) {
            int c = idx % 48;
            int t = idx / 48;
            int ii = t % ICH, o = t / ICH;
            ws[idx] = we[((size_t)(o0g + o) * I + (i0 + ii)) * 48 + c];
        }
        __syncthreads();
        #pragma unroll
        for (int ii = 0; ii < ICH; ii++) {
            u64 wv[OGO];
            #pragma unroll
            for (int j = 0; j < OGO; j++)
                wv[j] = *(const u64*)(ws + ((og * OGO + j) * ICH + ii) * 48 + 2 * cp);
            #pragma unroll
            for (int b = 0; b < 16; b++) {
                u64 xv = *(const u64*)(xs + (b * ICH + ii) * 48 + 2 * cp);
                #pragma unroll
                for (int j = 0; j < OGO; j++) fma2(acc[b][j], xv, wv[j]);
            }
        }
    }
    const int c = 2 * cp;
    #pragma unroll
    for (int b = 0; b < 16; b++)
        #pragma unroll
        for (int j = 0; j < OGO; j++) {
            float lo, hi;
            unpack2(acc[b][j], lo, hi);
            size_t base = ((size_t)(b0 + b) * O + (o0g + og * OGO + j)) * 45;
            if (c < 45)     y[base + c]     = lo;
            if (c + 1 < 45) y[base + c + 1] = hi;
        }
}

// ---------------- nonlin v3: persistent, 512 thr, 4-row x 7-pair tiles ----------------
// smem: bi2 u64[45][56] | bs2 u64[100][24] | ys f[256][46] | ts f[256][101]
#define NL_SMEM (20160 + 19200 + 47104 + 103424)

template<int OO, int O, int OS>
__global__ void __launch_bounds__(512, 1)
nonlin3(const float* __restrict__ y, const float* __restrict__ skip,
        const float* __restrict__ isft, const float* __restrict__ sft,
        float* __restrict__ out)
{
    extern __shared__ char smraw[];
    u64*   bi2 = (u64*)smraw;                 // [45][56]  isft, d-pairs packed
    u64*   bs2 = bi2 + 45 * 56;               // [100][24] sft,  c-pairs packed
    float* ys  = (float*)(bs2 + 100 * 24);    // [256][46]
    float* ts  = ys + 256 * 46;               // [256][101]

    const int tid = threadIdx.x;
    const int rg  = tid >> 3;                 // 64 row-groups of 4 rows
    const int pg  = tid & 7;                  // 8 pair-groups

    // stage B matrices once per CTA
    for (int idx = tid; idx < 45 * 56; idx += 512) {
        int k = idx / 56, p = idx % 56;
        float a = 0.f, b = 0.f;
        if (2 * p < 100) {
            a = isft[(2 * p) * 45 + k];
            b = isft[(2 * p + 1) * 45 + k];
        }
        bi2[idx] = pack2(a, b);
    }
    for (int idx = tid; idx < 100 * 24; idx += 512) {
        int d = idx / 24, p = idx % 24;
        int c = 2 * p;
        float a = (c < 45)     ? sft[c * 100 + d]       : 0.f;
        float b = (c + 1 < 45) ? sft[(c + 1) * 100 + d] : 0.f;
        bs2[idx] = pack2(a, b);
    }
    __syncthreads();

    const int NT = (BATCH * OO) / 256;
    for (int tile = blockIdx.x; tile < NT; tile += gridDim.x) {
        // stage input rows (concat resolved here)
        for (int idx = tid; idx < 256 * 45; idx += 512) {
            int r = idx / 45, cc = idx % 45;
            int gr = tile * 256 + r;
            int b = gr / OO, oo = gr % OO;
            float v;
            if (OS == 0 || oo < O) v = y[((size_t)b * O + oo) * 45 + cc];
            else                   v = skip[((size_t)b * OS + (oo - O)) * 45 + cc];
            ys[r * 46 + cc] = v;
        }
        __syncthreads();

        // GEMM1: t[r][d] = sum_c ys[r][c]*isft[d][c]; 4 rows x 7 d-pairs/thread
        {
            u64 acc[4][7];
            #pragma unroll
            for (int j = 0; j < 4; j++)
                #pragma unroll
                for (int q = 0; q < 7; q++) acc[j][q] = 0ull;

            const float* yrow = ys + rg * 4 * 46;
            const u64*   bb   = bi2 + pg * 7;
            #pragma unroll 3
            for (int k = 0; k < 45; k++) {
                u64 ya[4];
                #pragma unroll
                for (int j = 0; j < 4; j++) {
                    float v = yrow[j * 46 + k];
                    ya[j] = pack2(v, v);
                }
                u64 bv[7];
                #pragma unroll
                for (int q = 0; q < 7; q++) bv[q] = bb[k * 56 + q];
                #pragma unroll
                for (int j = 0; j < 4; j++)
                    #pragma unroll
                    for (int q = 0; q < 7; q++) fma2(acc[j][q], ya[j], bv[q]);
            }
            #pragma unroll
            for (int j = 0; j < 4; j++)
                #pragma unroll
                for (int q = 0; q < 7; q++) {
                    int col = 2 * (pg * 7 + q);
                    if (col < 100) {
                        float lo, hi;
                        unpack2(acc[j][q], lo, hi);
                        int r = rg * 4 + j;
                        ts[r * 101 + col]     = fmaxf(lo, 0.f);
                        ts[r * 101 + col + 1] = fmaxf(hi, 0.f);
                    }
                }
        }
        __syncthreads();

        // GEMM2: o[r][c] = sum_d ts[r][d]*sft[c][d]; 4 rows x 3 c-pairs/thread
        {
            u64 acc2[4][3];
            #pragma unroll
            for (int j = 0; j < 4; j++)
                #pragma unroll
                for (int q = 0; q < 3; q++) acc2[j][q] = 0ull;

            const float* trow = ts + rg * 4 * 101;
            const u64*   bb2  = bs2 + pg * 3;
            #pragma unroll 2
            for (int k = 0; k < 100; k++) {
                u64 ta[4];
                #pragma unroll
                for (int j = 0; j < 4; j++) {
                    float v = trow[j * 101 + k];
                    ta[j] = pack2(v, v);
                }
                u64 bv[3];
                #pragma unroll
                for (int q = 0; q < 3; q++) bv[q] = bb2[k * 24 + q];
                #pragma unroll
                for (int j = 0; j < 4; j++)
                    #pragma unroll
                    for (int q = 0; q < 3; q++) fma2(acc2[j][q], ta[j], bv[q]);
            }
            __syncthreads();   // ts free; also ys readers of prev phase done
            #pragma unroll
            for (int j = 0; j < 4; j++)
                #pragma unroll
                for (int q = 0; q < 3; q++) {
                    int c = 2 * (pg * 3 + q);
                    if (c < 45) {
                        float lo, hi;
                        unpack2(acc2[j][q], lo, hi);
                        int r = rg * 4 + j;
                        ys[r * 46 + c]     = lo;
                        ys[r * 46 + c + 1] = hi;
                    }
                }
        }
        __syncthreads();
        size_t base = (size_t)tile * 256 * 45;
        for (int idx = tid; idx < 256 * 45; idx += 512)
            out[base + idx] = ys[(idx / 45) * 46 + idx % 45];
        __syncthreads();
    }
}

// ---------------- final sconv ----------------
__global__ void final_sconv(const float* __restrict__ d4,
                            const float* __restrict__ we,
                            float* __restrict__ out)
{
    int idx = blockIdx.x * blockDim.x + threadIdx.x;
    if (idx >= BATCH * NCOEF) return;
    int c = idx % NCOEF;
    int b = idx / NCOEF;
    float acc = 0.f;
    #pragma unroll
    for (int i = 0; i < 16; i++)
        acc += d4[((size_t)b * 16 + i) * 45 + c] * we[i * 48 + c];
    out[idx] = acc;
}

// ---------------- launch helpers ----------------
template<int I, int O>
static void run_sconv(const float* in, const float* we, float* y)
{
    constexpr int OCTA = (O >= 32) ? 32 : 16;
    constexpr int ICH  = (I < 8) ? I : 8;
    size_t smem = (size_t)(16 + OCTA) * ICH * 48 * 4;
    auto kf = sconv3<I, O>;
    cudaFuncSetAttribute(kf, cudaFuncAttributeMaxDynamicSharedMemorySize, (int)smem);
    dim3 grid(BATCH / 16, O / OCTA);
    kf<<<grid, 192, smem>>>(in, we, y);
}

template<int OO, int O, int OS>
static void run_nonlin(const float* y, const float* skip,
                       const float* isft, const float* sft, float* out)
{
    auto kf = nonlin3<OO, O, OS>;
    cudaFuncSetAttribute(kf, cudaFuncAttributeMaxDynamicSharedMemorySize, NL_SMEM);
    kf<<<148, 512, NL_SMEM>>>(y, skip, isft, sft, out);
}

extern "C" void kernel_launch(void* const* d_in, const int* in_sizes, int n_in,
                              void* d_out, int out_size)
{
    const float* x    = (const float*)d_in[0];
    const float* sft  = (const float*)d_in[1];
    const float* isft = (const float*)d_in[2];
    const float* w[9];
    for (int k = 0; k < 9; k++) w[k] = (const float*)d_in[3 + k];
    const int* ls = (const int*)d_in[12];
    float* out = (float*)d_out;

    float *we, *yb, *e1, *e2, *e3, *e4, *d1, *d2, *d3, *d4;
    cudaGetSymbolAddress((void**)&we, g_we);
    cudaGetSymbolAddress((void**)&yb, g_yb);
    cudaGetSymbolAddress((void**)&e1, g_e1);
    cudaGetSymbolAddress((void**)&e2, g_e2);
    cudaGetSymbolAddress((void**)&e3, g_e3);
    cudaGetSymbolAddress((void**)&e4, g_e4);
    cudaGetSymbolAddress((void**)&d1, g_d1);
    cudaGetSymbolAddress((void**)&d2, g_d2);
    cudaGetSymbolAddress((void**)&d3, g_d3);
    cudaGetSymbolAddress((void**)&d4, g_d4);

    static const int w_off[9] = {0, 3072, 27648, 125952, 519168,
                                 912384, 1108992, 1158144, 1182720};

    expand_all_kernel<<<(1183488 + 255) / 256, 256>>>(
        w[0], w[1], w[2], w[3], w[4], w[5], w[6], w[7], w[8], ls, we);

    run_sconv<4, 16>(x, we + w_off[0], yb);
    run_nonlin<16, 16, 0>(yb, yb, isft, sft, e1);

    run_sconv<16, 32>(e1, we + w_off[1], yb);
    run_nonlin<32, 32, 0>(yb, yb, isft, sft, e2);

    run_sconv<32, 64>(e2, we + w_off[2], yb);
    run_nonlin<64, 64, 0>(yb, yb, isft, sft, e3);

    run_sconv<64, 128>(e3, we + w_off[3], yb);
    run_nonlin<128, 128, 0>(yb, yb, isft, sft, e4);

    run_sconv<128, 64>(e4, we + w_off[4], yb);
    run_nonlin<128, 64, 64>(yb, e3, isft, sft, d1);

    run_sconv<128, 32>(d1, we + w_off[5], yb);
    run_nonlin<64, 32, 32>(yb, e2, isft, sft, d2);

    run_sconv<64, 16>(d2, we + w_off[6], yb);
    run_nonlin<32, 16, 16>(yb, e1, isft, sft, d3);

    run_sconv<32, 16>(d3, we + w_off[7], yb);
    run_nonlin<16, 16, 0>(yb, yb, isft, sft, d4);

    final_sconv<<<(BATCH * NCOEF + 255) / 256, 256>>>(d4, we + w_off[8], out);
}

// round 7
// speedup vs baseline: 1.4150x; 1.0071x over previous
// SCNNModel — fp32x2 v4: padded-48 activations, raw-w5 smem sconv (LDG.64 x),
// transposed-operand persistent nonlin. Plain sm_100 target (no tcgen05).
#include <cuda_runtime.h>
#include <math.h>
#include <stdint.h>

#define BATCH 16384
#define PI_F 3.14159265358979323846f
typedef unsigned long long u64;

// ---------------- device scratch (activations padded to stride 48) ----------------
__device__ float g_x48[BATCH * 4   * 48];
__device__ float g_yb [BATCH * 128 * 48];
__device__ float g_e1 [BATCH * 16  * 48];
__device__ float g_e2 [BATCH * 32  * 48];
__device__ float g_e3 [BATCH * 64  * 48];
__device__ float g_e4 [BATCH * 128 * 48];
__device__ float g_d1 [BATCH * 128 * 48];
__device__ float g_d2 [BATCH * 64  * 48];
__device__ float g_d3 [BATCH * 32  * 48];
__device__ float g_d4 [BATCH * 16  * 48];

// ---------------- f32x2 helpers ----------------
__device__ __forceinline__ u64 pack2(float x, float y) {
    u64 r;
    asm("mov.b64 %0, {%1, %2};" : "=l"(r) : "f"(x), "f"(y));
    return r;
}
__device__ __forceinline__ void unpack2(u64 v, float& x, float& y) {
    asm("mov.b64 {%0, %1}, %2;" : "=f"(x), "=f"(y) : "l"(v));
}
__device__ __forceinline__ void fma2(u64& d, u64 a, u64 b) {
    asm("fma.rn.f32x2 %0, %1, %2, %0;" : "+l"(d) : "l"(a), "l"(b));
}
// degree-half index per coefficient (structure of _make_ls)
__device__ __forceinline__ int lh_of(int c) {
    return (c < 1) ? 0 : (c < 6) ? 1 : (c < 15) ? 2 : (c < 28) ? 3 : 4;
}

// ---------------- pad input x [B][4][45] -> [B][4][48] ----------------
__global__ void pad48(const float* __restrict__ x, float* __restrict__ xp)
{
    int idx = blockIdx.x * blockDim.x + threadIdx.x;
    if (idx >= BATCH * 4 * 48) return;
    int c = idx % 48;
    int t = idx / 48;
    xp[idx] = (c < 45) ? x[t * 45 + c] : 0.f;
}

// ---------------- sconv v4: raw w[o][i][5] (lfac folded) in smem, x via LDG.64 ----
template<int I, int O>
__global__ void __launch_bounds__(192, 2)
sconv4(const float* __restrict__ x, const float* __restrict__ w,
       float* __restrict__ y)
{
    constexpr int OCTA = (O >= 32) ? 32 : 16;
    constexpr int OGO  = OCTA / 8;                 // 4 or 2
    constexpr int IH   = (I > 64) ? 64 : I;
    __shared__ float w5s[OCTA * IH * 5];           // <= 40 KB

    const int tid = threadIdx.x;
    const int cp  = tid % 24;
    const int og  = tid / 24;
    const int b0  = blockIdx.x * 8;
    const int o0g = blockIdx.y * OCTA;
    const int c0  = 2 * cp;
    const int lh0 = lh_of(c0), lh1 = lh_of(c0 + 1);

    u64 acc[8][OGO];
    #pragma unroll
    for (int b = 0; b < 8; b++)
        #pragma unroll
        for (int j = 0; j < OGO; j++) acc[b][j] = 0ull;

    for (int ih0 = 0; ih0 < I; ih0 += IH) {
        __syncthreads();
        for (int idx = tid; idx < OCTA * IH * 5; idx += 192) {
            int lh = idx % 5;
            int t  = idx / 5;
            int ii = t % IH, o = t / IH;
            float lf = sqrtf(PI_F / (4.f * (float)lh + 1.f));
            w5s[idx] = w[((size_t)(o0g + o) * I + ih0 + ii) * 5 + lh] * lf;
        }
        __syncthreads();
        #pragma unroll 2
        for (int ii = 0; ii < IH; ii++) {
            u64 xv[8];
            #pragma unroll
            for (int b = 0; b < 8; b++)
                xv[b] = *(const u64*)(x + ((size_t)(b0 + b) * I + ih0 + ii) * 48 + c0);
            u64 wv[OGO];
            #pragma unroll
            for (int j = 0; j < OGO; j++) {
                const float* wp = w5s + ((og * OGO + j) * IH + ii) * 5;
                wv[j] = pack2(wp[lh0], wp[lh1]);
            }
            #pragma unroll
            for (int b = 0; b < 8; b++)
                #pragma unroll
                for (int j = 0; j < OGO; j++) fma2(acc[b][j], xv[b], wv[j]);
        }
    }
    #pragma unroll
    for (int b = 0; b < 8; b++)
        #pragma unroll
        for (int j = 0; j < OGO; j++)
            *(u64*)(y + ((size_t)(b0 + b) * O + o0g + og * OGO + j) * 48 + c0) = acc[b][j];
}

// ---------------- nonlin v4: persistent, transposed smem operands ----------------
// smem: bi2 u64[45][56] | bs2 u64[100][24] | ysT f[45][257] (reused outs f[256][49]) | tsT f[100][257]
#define YS_FLOATS 12544
#define NL_SMEM ((45*56 + 100*24) * 8 + (YS_FLOATS + 100*257) * 4)

template<int OO, int O, int OS>
__global__ void __launch_bounds__(512, 1)
nonlin4(const float* __restrict__ y, const float* __restrict__ skip,
        const float* __restrict__ isft, const float* __restrict__ sft,
        float* __restrict__ out)
{
    extern __shared__ char smraw[];
    u64*   bi2 = (u64*)smraw;                  // [45][56]  isft d-pairs
    u64*   bs2 = bi2 + 45 * 56;                // [100][24] sft c-pairs
    float* ysT = (float*)(bs2 + 100 * 24);     // [45][257] ; reused as outs [256][49]
    float* tsT = ysT + YS_FLOATS;              // [100][257]

    const int tid = threadIdx.x;
    const int w   = tid >> 5;
    const int rg  = tid & 31;
    const int rh  = (w & 1) * 128;             // row half
    const int blk = w >> 1;                    // 0..7 pair block

    for (int idx = tid; idx < 45 * 56; idx += 512) {
        int k = idx / 56, dp = idx % 56;
        float a = (2 * dp     < 100) ? isft[(2 * dp) * 45 + k]     : 0.f;
        float b = (2 * dp + 1 < 100) ? isft[(2 * dp + 1) * 45 + k] : 0.f;
        bi2[idx] = pack2(a, b);
    }
    for (int idx = tid; idx < 100 * 24; idx += 512) {
        int d = idx / 24, cq = idx % 24;
        float a = (2 * cq     < 45) ? sft[(2 * cq) * 100 + d]     : 0.f;
        float b = (2 * cq + 1 < 45) ? sft[(2 * cq + 1) * 100 + d] : 0.f;
        bs2[idx] = pack2(a, b);
    }
    __syncthreads();

    const int NT = (BATCH * OO) / 256;
    for (int tile = blockIdx.x; tile < NT; tile += gridDim.x) {
        // ---- stage y tile transposed: ysT[c][r] (coalesced reads) ----
        for (int idx = tid; idx < 256 * 48; idx += 512) {
            int r = idx / 48, c = idx % 48;
            if (c < 45) {
                int gr = tile * 256 + r;
                int b = gr / OO, oo = gr % OO;
                float v;
                if (OS == 0 || oo < O) v = y[((size_t)b * O + oo) * 48 + c];
                else                   v = skip[((size_t)b * OS + (oo - O)) * 48 + c];
                ysT[c * 257 + r] = v;
            }
        }
        __syncthreads();

        // ---- GEMM1: t[r][d] = sum_k ys[r][k]*isft[d][k]; 4 rows x 7 d-pairs ----
        {
            u64 acc[4][7];
            #pragma unroll
            for (int j = 0; j < 4; j++)
                #pragma unroll
                for (int q = 0; q < 7; q++) acc[j][q] = 0ull;

            #pragma unroll 3
            for (int k = 0; k < 45; k++) {
                u64 av[4];
                #pragma unroll
                for (int j = 0; j < 4; j++) {
                    float v = ysT[k * 257 + rh + rg + 32 * j];
                    av[j] = pack2(v, v);
                }
                u64 bv[7];
                #pragma unroll
                for (int q = 0; q < 7; q++) bv[q] = bi2[k * 56 + blk * 7 + q];
                #pragma unroll
                for (int j = 0; j < 4; j++)
                    #pragma unroll
                    for (int q = 0; q < 7; q++) fma2(acc[j][q], av[j], bv[q]);
            }
            #pragma unroll
            for (int q = 0; q < 7; q++) {
                int d = 2 * (blk * 7 + q);
                #pragma unroll
                for (int j = 0; j < 4; j++) {
                    float lo, hi;
                    unpack2(acc[j][q], lo, hi);
                    int r = rh + rg + 32 * j;
                    if (d < 100)     tsT[d * 257 + r]       = fmaxf(lo, 0.f);
                    if (d + 1 < 100) tsT[(d + 1) * 257 + r] = fmaxf(hi, 0.f);
                }
            }
        }
        __syncthreads();

        // ---- GEMM2: o[r][c] = sum_d t[r][d]*sft[c][d]; 4 rows x 3 c-pairs ----
        {
            u64 acc2[4][3];
            #pragma unroll
            for (int j = 0; j < 4; j++)
                #pragma unroll
                for (int q = 0; q < 3; q++) acc2[j][q] = 0ull;

            #pragma unroll 2
            for (int k = 0; k < 100; k++) {
                u64 av[4];
                #pragma unroll
                for (int j = 0; j < 4; j++) {
                    float v = tsT[k * 257 + rh + rg + 32 * j];
                    av[j] = pack2(v, v);
                }
                u64 bv[3];
                #pragma unroll
                for (int q = 0; q < 3; q++) bv[q] = bs2[k * 24 + blk * 3 + q];
                #pragma unroll
                for (int j = 0; j < 4; j++)
                    #pragma unroll
                    for (int q = 0; q < 3; q++) fma2(acc2[j][q], av[j], bv[q]);
            }
            // write into outs (reuses ysT region; GEMM1 readers done at barrier above)
            float* outs = ysT;
            #pragma unroll
            for (int q = 0; q < 3; q++) {
                int c = 2 * (blk * 3 + q);
                #pragma unroll
                for (int j = 0; j < 4; j++) {
                    float lo, hi;
                    unpack2(acc2[j][q], lo, hi);
                    int r = rh + rg + 32 * j;
                    outs[r * 49 + c]     = lo;   // c <= 46
                    outs[r * 49 + c + 1] = hi;   // c+1 <= 47 (pad cols zero via bs2 pad)
                }
            }
        }
        __syncthreads();
        // ---- coalesced copy to padded-48 global ----
        {
            const float* outs = ysT;
            size_t base = (size_t)tile * 256 * 48;
            for (int idx = tid; idx < 256 * 48; idx += 512)
                out[base + idx] = outs[(idx / 48) * 49 + idx % 48];
        }
        __syncthreads();
    }
}

// ---------------- final sconv: out[b][c] = sum_i d4[b][i][c]*w9[i][lh(c)]*lfac ----
__global__ void final_sconv(const float* __restrict__ d4,
                            const float* __restrict__ w9,
                            float* __restrict__ out)
{
    __shared__ float ws[16 * 5];
    int tid = threadIdx.x;
    if (tid < 80) {
        int lh = tid % 5;
        float lf = sqrtf(PI_F / (4.f * (float)lh + 1.f));
        ws[tid] = w9[tid] * lf;
    }
    __syncthreads();
    int idx = blockIdx.x * blockDim.x + tid;
    if (idx >= BATCH * 45) return;
    int c = idx % 45;
    int b = idx / 45;
    int lh = lh_of(c);
    float acc = 0.f;
    #pragma unroll
    for (int i = 0; i < 16; i++)
        acc += d4[((size_t)b * 16 + i) * 48 + c] * ws[i * 5 + lh];
    out[idx] = acc;
}

// ---------------- launch helpers ----------------
template<int I, int O>
static void run_sconv(const float* in, const float* w, float* y)
{
    constexpr int OCTA = (O >= 32) ? 32 : 16;
    dim3 grid(BATCH / 8, O / OCTA);
    sconv4<I, O><<<grid, 192>>>(in, w, y);
}

template<int OO, int O, int OS>
static void run_nonlin(const float* y, const float* skip,
                       const float* isft, const float* sft, float* out)
{
    auto kf = nonlin4<OO, O, OS>;
    cudaFuncSetAttribute(kf, cudaFuncAttributeMaxDynamicSharedMemorySize, NL_SMEM);
    kf<<<148, 512, NL_SMEM>>>(y, skip, isft, sft, out);
}

extern "C" void kernel_launch(void* const* d_in, const int* in_sizes, int n_in,
                              void* d_out, int out_size)
{
    const float* x    = (const float*)d_in[0];
    const float* sft  = (const float*)d_in[1];
    const float* isft = (const float*)d_in[2];
    const float* w[9];
    for (int k = 0; k < 9; k++) w[k] = (const float*)d_in[3 + k];
    float* out = (float*)d_out;

    float *x48, *yb, *e1, *e2, *e3, *e4, *d1, *d2, *d3, *d4;
    cudaGetSymbolAddress((void**)&x48, g_x48);
    cudaGetSymbolAddress((void**)&yb, g_yb);
    cudaGetSymbolAddress((void**)&e1, g_e1);
    cudaGetSymbolAddress((void**)&e2, g_e2);
    cudaGetSymbolAddress((void**)&e3, g_e3);
    cudaGetSymbolAddress((void**)&e4, g_e4);
    cudaGetSymbolAddress((void**)&d1, g_d1);
    cudaGetSymbolAddress((void**)&d2, g_d2);
    cudaGetSymbolAddress((void**)&d3, g_d3);
    cudaGetSymbolAddress((void**)&d4, g_d4);

    pad48<<<(BATCH * 4 * 48 + 255) / 256, 256>>>(x, x48);

    run_sconv<4, 16>(x48, w[0], yb);
    run_nonlin<16, 16, 0>(yb, yb, isft, sft, e1);

    run_sconv<16, 32>(e1, w[1], yb);
    run_nonlin<32, 32, 0>(yb, yb, isft, sft, e2);

    run_sconv<32, 64>(e2, w[2], yb);
    run_nonlin<64, 64, 0>(yb, yb, isft, sft, e3);

    run_sconv<64, 128>(e3, w[3], yb);
    run_nonlin<128, 128, 0>(yb, yb, isft, sft, e4);

    run_sconv<128, 64>(e4, w[4], yb);
    run_nonlin<128, 64, 64>(yb, e3, isft, sft, d1);

    run_sconv<128, 32>(d1, w[5], yb);
    run_nonlin<64, 32, 32>(yb, e2, isft, sft, d2);

    run_sconv<64, 16>(d2, w[6], yb);
    run_nonlin<32, 16, 16>(yb, e1, isft, sft, d3);

    run_sconv<32, 16>(d3, w[7], yb);
    run_nonlin<16, 16, 0>(yb, yb, isft, sft, d4);

    final_sconv<<<(BATCH * 45 + 255) / 256, 256>>>(d4, w[8], out);
}